// round 8
// baseline (speedup 1.0000x reference)
#include <cuda_runtime.h>
#include <cuda_fp16.h>
#include <cstdint>

// Per-CTA smem (2 CTAs/SM):
#define SM_U(s)   ((s) * 16384)              // U ring2: [n=128][k=64] f16, swizzled
#define SM_A(s)   (32768 + (s) * 16384)      // A ring3: staged chunk, fragment order
#define SM_PV     81920                      // prev [h=64][n=128] f32 = 32KB
#define SM_RED    114688                     // 16 f32
#define SM_TOTAL  114752

// W in m16n8k16 A-fragment order: [g=L*40+m][rb][ks][lane] x 8 halfs (16B)
__device__ __align__(16) __half g_wA[983040];

__device__ __forceinline__ uint32_t sh_addr(const void* p) {
    return (uint32_t)__cvta_generic_to_shared(p);
}

__device__ __forceinline__ void mma16816(float* c, const uint4& a,
                                         uint32_t bq0, uint32_t bq1) {
    asm volatile(
        "mma.sync.aligned.m16n8k16.row.col.f32.f16.f16.f32 "
        "{%0,%1,%2,%3}, {%4,%5,%6,%7}, {%8,%9}, {%0,%1,%2,%3};"
        : "+f"(c[0]), "+f"(c[1]), "+f"(c[2]), "+f"(c[3])
        : "r"(a.x), "r"(a.y), "r"(a.z), "r"(a.w), "r"(bq0), "r"(bq1));
}

#define LDMX4(r0, r1, r2, r3, ad) \
    asm volatile("ldmatrix.sync.aligned.m8n8.x4.shared.b16 {%0,%1,%2,%3}, [%4];" \
        : "=r"(r0), "=r"(r1), "=r"(r2), "=r"(r3) : "r"(ad))

#define CPA16(dst, src) \
    asm volatile("cp.async.cg.shared.global [%0], [%1], 16;" :: "r"(dst), "l"(src))

// w[o][k][m] f32 (k < H real) -> g_wA fragment order, f16
__global__ void prep_w(const float* __restrict__ w, int H, int gBase) {
    int idx = blockIdx.x * blockDim.x + threadIdx.x;   // < 40*8192
    if (idx >= 40 * 8192) return;
    int e    = idx & 7;
    int lane = (idx >> 3) & 31;
    int ks   = (idx >> 8) & 3;
    int rb   = (idx >> 10) & 7;
    int m    = idx >> 13;
    int r = rb * 16 + (lane >> 2) + ((e >> 1) & 1) * 8;
    int k = ks * 16 + (lane & 3) * 2 + (e & 1) + ((e >> 2) & 1) * 8;
    float v = (k < H) ? w[r * (H * 40) + k * 40 + m] : 0.f;
    g_wA[(size_t)(gBase + m) * 8192 + (idx & 8191)] = __float2half(v);
}

__global__ void __launch_bounds__(256, 2) cin_mma(
    const float* __restrict__ x,
    const float* __restrict__ b0, const float* __restrict__ b1,
    const float* __restrict__ b2,
    const float* __restrict__ wl, float* __restrict__ out)
{
    extern __shared__ char smp[];
    float* pvS = (float*)(smp + SM_PV);
    float* red = (float*)(smp + SM_RED);
    int t = threadIdx.x, w = t >> 5, l = t & 31;
    int bb = blockIdx.x * 8;

    // ---- gen mapping: thread covers column gn, k-range [gh, gh+32) ----
    int gn = t & 127;
    int gh = (t >> 7) * 32;
    const float* xcolg = x + (size_t)(bb + (gn >> 4)) * 640 + (gn & 15);

    float pv[32];
    #pragma unroll
    for (int i = 0; i < 32; i++) {
        int h = gh + i;
        pv[i] = (h < 40) ? __ldg(xcolg + h * 16) : 0.f;   // layer-0 prev = x
    }

    uint32_t goff[4];
    #pragma unroll
    for (int j = 0; j < 4; j++)
        goff[j] = (uint32_t)(gn * 128 + ((((gh >> 3) + j) ^ (gn & 7)) * 16));

    // ---- MMA mapping: warp tile = 64 rows (rg) x 32 cols (cg); L2: 64x16 ----
    int rg = w >> 2, cg = w & 3;
    int kh = (l >> 3) & 1;
    int lrow = ((l >> 4) & 1) * 8 + (l & 7);

    float C[4][4][4];
    float accA0 = 0.f, accA1 = 0.f, accL2 = 0.f;
    const float* biasArr[3] = { b0, b1, b2 };

    for (int L = 0; L < 3; L++) {
        bool isL2 = (L == 2);
        #pragma unroll
        for (int rbi = 0; rbi < 4; rbi++)
            #pragma unroll
            for (int nt = 0; nt < 4; nt++)
                #pragma unroll
                for (int i = 0; i < 4; i++) C[rbi][nt][i] = 0.f;
        int g0 = L * 40;

        // prefetch A(chunk 0) into slot 0 (L2: only live half, rows 64..127)
        {
            const char* src = (const char*)g_wA + (size_t)g0 * 16384 + t * 16;
            uint32_t dst = sh_addr(smp + SM_A(0)) + (uint32_t)(t * 16);
            if (!isL2) { CPA16(dst, src); CPA16(dst + 4096, src + 4096); }
            CPA16(dst + 8192, src + 8192);
            CPA16(dst + 12288, src + 12288);
            asm volatile("cp.async.commit_group;" ::: "memory");
        }

        for (int c = 0; c <= 40; c++) {
            asm volatile("cp.async.wait_group 0;" ::: "memory");
            __syncthreads();   // A(c) staged & gen(c-1)/reads(c-2) ordered

            if (c + 1 < 40) {  // prefetch A(c+1) -> slot (c+1)%3, in flight this iter
                const char* src = (const char*)g_wA +
                                  (size_t)(g0 + c + 1) * 16384 + t * 16;
                uint32_t dst = sh_addr(smp + SM_A((c + 1) % 3)) + (uint32_t)(t * 16);
                if (!isL2) { CPA16(dst, src); CPA16(dst + 4096, src + 4096); }
                CPA16(dst + 8192, src + 8192);
                CPA16(dst + 12288, src + 12288);
                asm volatile("cp.async.commit_group;" ::: "memory");
            }

            if (c < 40) {      // gen U(c) -> buf c&1, overlaps MMA(c-1) below
                float xv = __ldg(xcolg + c * 16);
                char* Ub = smp + SM_U(c & 1);
                #pragma unroll
                for (int j = 0; j < 4; j++) {
                    uint4 Hq; uint32_t* hh = (uint32_t*)&Hq;
                    #pragma unroll
                    for (int q = 0; q < 4; q++) {
                        __half2 h2 = __floats2half2_rn(xv * pv[j * 8 + q * 2],
                                                       xv * pv[j * 8 + q * 2 + 1]);
                        hh[q] = *(uint32_t*)&h2;
                    }
                    *(uint4*)(Ub + goff[j]) = Hq;
                }
            }

            if (c > 0) {       // MMA chunk c-1: U buf (c-1)&1, A slot (c-1)%3
                int cc = c - 1;
                uint32_t ub = sh_addr(smp + SM_U(cc & 1));
                const char* Ab = smp + SM_A(cc % 3);
                if (!isL2) {
                    #pragma unroll
                    for (int ks = 0; ks < 4; ks++) {
                        uint32_t br[4][2];
                        #pragma unroll
                        for (int ntp = 0; ntp < 2; ntp++) {
                            int n = cg * 32 + ntp * 16 + lrow;
                            uint32_t ad = ub + (uint32_t)(n * 128) +
                                          (uint32_t)((((ks * 2 + kh) ^ (n & 7)) * 16));
                            LDMX4(br[ntp * 2][0], br[ntp * 2][1],
                                  br[ntp * 2 + 1][0], br[ntp * 2 + 1][1], ad);
                        }
                        #pragma unroll
                        for (int rbi = 0; rbi < 4; rbi++) {
                            uint4 a = *(const uint4*)(Ab +
                                (((rg * 4 + rbi) * 4 + ks) * 32 + l) * 16);
                            #pragma unroll
                            for (int nt = 0; nt < 4; nt++)
                                mma16816(C[rbi][nt], a, br[nt][0], br[nt][1]);
                        }
                    }
                } else {       // rows 64..127; warp w covers cols w*16..+16
                    #pragma unroll
                    for (int ks = 0; ks < 4; ks++) {
                        uint32_t br[2][2];
                        int n = w * 16 + lrow;
                        uint32_t ad = ub + (uint32_t)(n * 128) +
                                      (uint32_t)((((ks * 2 + kh) ^ (n & 7)) * 16));
                        LDMX4(br[0][0], br[0][1], br[1][0], br[1][1], ad);
                        #pragma unroll
                        for (int rbi = 0; rbi < 4; rbi++) {
                            uint4 a = *(const uint4*)(Ab +
                                (((4 + rbi) * 4 + ks) * 32 + l) * 16);
                            #pragma unroll
                            for (int nt = 0; nt < 2; nt++)
                                mma16816(C[rbi][nt], a, br[nt][0], br[nt][1]);
                        }
                    }
                }
            }
        }

        // ---- epilogue ----
        const float* bp = biasArr[L];
        if (!isL2) {
            #pragma unroll
            for (int rbi = 0; rbi < 4; rbi++) {
                int r0 = (rg * 4 + rbi) * 16 + (l >> 2);
                float bv0 = __ldg(bp + r0), bv1 = __ldg(bp + r0 + 8);
                float wl0 = 0.f, wl1 = 0.f;
                if (rg == 1) {
                    wl0 = __ldg(wl + L * 64 + r0 - 64);
                    wl1 = __ldg(wl + L * 64 + r0 - 56);
                }
                #pragma unroll
                for (int nt = 0; nt < 4; nt++) {
                    int n0 = cg * 32 + nt * 8 + (l & 3) * 2;
                    float v0 = fmaxf(C[rbi][nt][0] + bv0, 0.f);
                    float v1 = fmaxf(C[rbi][nt][1] + bv0, 0.f);
                    float v2 = fmaxf(C[rbi][nt][2] + bv1, 0.f);
                    float v3 = fmaxf(C[rbi][nt][3] + bv1, 0.f);
                    if (rg == 0) {              // prev half -> pvS
                        pvS[r0 * 128 + n0]           = v0;
                        pvS[r0 * 128 + n0 + 1]       = v1;
                        pvS[(r0 + 8) * 128 + n0]     = v2;
                        pvS[(r0 + 8) * 128 + n0 + 1] = v3;
                    } else {                    // direct half -> weighted acc
                        float a = wl0 * (v0 + v1) + wl1 * (v2 + v3);
                        if (nt < 2) accA0 += a; else accA1 += a;
                    }
                }
            }
            __syncthreads();                    // pvS writes visible
            #pragma unroll
            for (int i = 0; i < 32; i++) pv[i] = pvS[(gh + i) * 128 + gn];
        } else {
            #pragma unroll
            for (int rbi = 0; rbi < 4; rbi++) {
                int r0 = (4 + rbi) * 16 + (l >> 2);
                float bv0 = __ldg(bp + r0), bv1 = __ldg(bp + r0 + 8);
                float wl0 = __ldg(wl + 128 + r0 - 64);
                float wl1 = __ldg(wl + 128 + r0 - 56);
                #pragma unroll
                for (int nt = 0; nt < 2; nt++) {
                    float v0 = fmaxf(C[rbi][nt][0] + bv0, 0.f);
                    float v1 = fmaxf(C[rbi][nt][1] + bv0, 0.f);
                    float v2 = fmaxf(C[rbi][nt][2] + bv1, 0.f);
                    float v3 = fmaxf(C[rbi][nt][3] + bv1, 0.f);
                    accL2 += wl0 * (v0 + v1) + wl1 * (v2 + v3);
                }
            }
        }
    }

    // ---- deterministic reduction (8 batches per CTA) ----
    #pragma unroll
    for (int off = 16; off > 0; off >>= 1) {
        accA0 += __shfl_xor_sync(0xffffffffu, accA0, off);
        accA1 += __shfl_xor_sync(0xffffffffu, accA1, off);
        accL2 += __shfl_xor_sync(0xffffffffu, accL2, off);
    }
    __syncthreads();
    if (l == 0) {
        if (rg == 1) { red[2 * cg] = accA0; red[2 * cg + 1] = accA1; }
        red[8 + w] = accL2;   // L2 warp w covers batch w
    }
    __syncthreads();
    if (t < 8) out[bb + t] = red[t] + red[8 + t];
}

extern "C" void kernel_launch(void* const* d_in, const int* in_sizes, int n_in,
                              void* d_out, int out_size) {
    const float* x  = (const float*)d_in[0];
    const float* w0 = (const float*)d_in[1];
    const float* b0 = (const float*)d_in[2];
    const float* w1 = (const float*)d_in[3];
    const float* b1 = (const float*)d_in[4];
    const float* w2 = (const float*)d_in[5];
    const float* b2 = (const float*)d_in[6];
    const float* wl = (const float*)d_in[7];
    float* out = (float*)d_out;

    cudaFuncSetAttribute(cin_mma, cudaFuncAttributeMaxDynamicSharedMemorySize,
                         SM_TOTAL);

    int np = 40 * 8192;
    prep_w<<<(np + 255) / 256, 256>>>(w0, 40, 0);
    prep_w<<<(np + 255) / 256, 256>>>(w1, 64, 40);
    prep_w<<<(np + 255) / 256, 256>>>(w2, 64, 80);

    cin_mma<<<256, 256, SM_TOTAL>>>(x, b0, b1, b2, wl, out);
}